// round 5
// baseline (speedup 1.0000x reference)
#include <cuda_runtime.h>
#include <stdint.h>

#define L 12288
#define NB 8                 // batch
#define WPR (L / 32)         // 384 bit-words per row
#define NWORDS (L * WPR)     // 4,718,592 words = 18.9 MB bit matrix

// -------- static device scratch (no runtime allocation allowed) --------
__device__ unsigned int g_bits[NWORDS];                 // packed mask, bit j of row i
__device__ __align__(16) float g_accJ[L * NB];          // [j][b] masked-adj-weighted sums
__device__ float g_cnt[L];                              // column counts
__device__ __align__(16) float g_pt[L * NB];            // predicts transposed [i][b]
__device__ float g_norm2[NB];                           // per-batch sum of diff^2
__device__ int g_ff;                                    // saw float-1.0 word
__device__ int g_fm;                                    // saw multi/odd word (byte layout)

// ---------------------------------------------------------------------
__global__ void k_zero() {
    const int n = L * NB + L + NB;
    for (int i = blockIdx.x * blockDim.x + threadIdx.x; i < n;
         i += gridDim.x * blockDim.x) {
        if (i < L * NB)             g_accJ[i] = 0.0f;
        else if (i < L * NB + L)    g_cnt[i - L * NB] = 0.0f;
        else                        g_norm2[i - L * NB - L] = 0.0f;
    }
    if (blockIdx.x == 0 && threadIdx.x == 0) { g_ff = 0; g_fm = 0; }
}

// Sniff the mask dtype from the first 4 MB viewed as 32-bit words.
// float32 mask: words are 0x00000000 / 0x3F800000.
// int32  mask: words are 0 / 1 only.
// byte   mask: words combine four 0/1 bytes -> values like 0x00010000 appear w.h.p.
__global__ void k_detect(const unsigned int* __restrict__ mw) {
    int ff = 0, fm = 0;
    const int N = 1 << 20;  // 1M words = 4MB, within every candidate layout
    for (int i = blockIdx.x * blockDim.x + threadIdx.x; i < N;
         i += gridDim.x * blockDim.x) {
        unsigned v = mw[i];
        if (v == 0x3F800000u) ff = 1;
        else if (v > 1u) fm = 1;
    }
    if (ff) g_ff = 1;   // racy idempotent stores are fine
    if (fm) g_fm = 1;
}

// pack the nonzero-ness of 4 bytes into a nibble
__device__ __forceinline__ unsigned nib4(unsigned v) {
    unsigned t = (v & 0x7F7F7F7Fu) + 0x7F7F7F7Fu;
    t = (t | v) & 0x80808080u;   // high bit per byte iff byte nonzero
    t >>= 7;                     // -> 0/1 bytes
    return (t * 0x01020408u) >> 24;  // pack to 4 LSBs
}

// Compress mask -> g_bits. One thread per 32-column word.
__global__ void k_convert(const unsigned char* __restrict__ maskb) {
    const bool bytemode = (g_fm && !g_ff);
    const int stride = gridDim.x * blockDim.x;
    if (bytemode) {
        for (int w = blockIdx.x * blockDim.x + threadIdx.x; w < NWORDS; w += stride) {
            const uint4* p = reinterpret_cast<const uint4*>(maskb) + (size_t)w * 2;
            uint4 x0 = p[0], x1 = p[1];
            unsigned bits = nib4(x0.x) | (nib4(x0.y) << 4) | (nib4(x0.z) << 8) |
                            (nib4(x0.w) << 12) | (nib4(x1.x) << 16) |
                            (nib4(x1.y) << 20) | (nib4(x1.z) << 24) |
                            (nib4(x1.w) << 28);
            g_bits[w] = bits;
        }
    } else {
        // 4-byte elements (int32 0/1 or float32 0.0/1.0): nonzero word => set bit
        for (int w = blockIdx.x * blockDim.x + threadIdx.x; w < NWORDS; w += stride) {
            const uint4* p = reinterpret_cast<const uint4*>(maskb) + (size_t)w * 8;
            unsigned bits = 0;
#pragma unroll
            for (int q = 0; q < 8; q++) {
                uint4 x = p[q];
                bits |= (x.x ? 1u : 0u) << (4 * q);
                bits |= (x.y ? 1u : 0u) << (4 * q + 1);
                bits |= (x.z ? 1u : 0u) << (4 * q + 2);
                bits |= (x.w ? 1u : 0u) << (4 * q + 3);
            }
            g_bits[w] = bits;
        }
    }
}

// predicts [B][L] -> g_pt [L][B] so the scan can broadcast-load a row as 2x float4
__global__ void k_transpose(const float* __restrict__ P) {
    int i = blockIdx.x * blockDim.x + threadIdx.x;
    if (i < L) {
        float4 a, b;
        a.x = P[0 * L + i]; a.y = P[1 * L + i]; a.z = P[2 * L + i]; a.w = P[3 * L + i];
        b.x = P[4 * L + i]; b.y = P[5 * L + i]; b.z = P[6 * L + i]; b.w = P[7 * L + i];
        reinterpret_cast<float4*>(g_pt)[i * 2 + 0] = a;
        reinterpret_cast<float4*>(g_pt)[i * 2 + 1] = b;
    }
}

// Sparse scan: grid (12 column-tiles x 32 row-splits), 256 threads.
// Block owns 1024 columns; shared accumulators; set bits are rare (~1%).
#define JT 1024
#define IBS 32
#define ROWS_PER_BLK (L / IBS)   // 384

__global__ __launch_bounds__(256) void k_scan(const float* __restrict__ adj) {
    __shared__ float s_acc[JT * NB];  // [jl][b]
    __shared__ float s_cnt[JT];

    for (int i = threadIdx.x; i < JT * NB; i += blockDim.x) s_acc[i] = 0.0f;
    for (int i = threadIdx.x; i < JT; i += blockDim.x) s_cnt[i] = 0.0f;
    __syncthreads();

    const int jb = blockIdx.x;            // 0..11
    const int ib = blockIdx.y;            // 0..31
    const int wl = threadIdx.x & 31;      // word lane within column tile
    const int rg = threadIdx.x >> 5;      // warp id -> row group (uniform per warp)
    const int i0 = ib * ROWS_PER_BLK;
    const unsigned int* bits = g_bits + jb * 32 + wl;
    const float* adjbase = adj + (size_t)jb * JT;

    for (int i = i0 + rg; i < i0 + ROWS_PER_BLK; i += 8) {
        unsigned word = bits[i * WPR];
        // warp-uniform broadcast of predicts row i
        float4 pA = reinterpret_cast<const float4*>(g_pt)[i * 2 + 0];
        float4 pB = reinterpret_cast<const float4*>(g_pt)[i * 2 + 1];
        const float* adjrow = adjbase + (size_t)i * L;
        while (word) {
            int p = __ffs(word) - 1;
            word &= word - 1;
            int jl = (wl << 5) + p;
            float a = __ldg(adjrow + jl);
            atomicAdd(&s_cnt[jl], 1.0f);
            float* acc = &s_acc[jl * NB];
            atomicAdd(acc + 0, a * pA.x);
            atomicAdd(acc + 1, a * pA.y);
            atomicAdd(acc + 2, a * pA.z);
            atomicAdd(acc + 3, a * pA.w);
            atomicAdd(acc + 4, a * pB.x);
            atomicAdd(acc + 5, a * pB.y);
            atomicAdd(acc + 6, a * pB.z);
            atomicAdd(acc + 7, a * pB.w);
        }
    }
    __syncthreads();

    for (int jl = threadIdx.x; jl < JT; jl += blockDim.x) {
        float c = s_cnt[jl];
        if (c != 0.0f) {
            int j = jb * JT + jl;
            atomicAdd(&g_cnt[j], c);
#pragma unroll
            for (int b = 0; b < NB; b++)
                atomicAdd(&g_accJ[j * NB + b], s_acc[jl * NB + b]);
        }
    }
}

// candidates -> diff -> per-batch sum of squares
__global__ __launch_bounds__(256) void k_finish(const float* __restrict__ P,
                                                const float* __restrict__ S) {
    __shared__ float sS[64];
    if (threadIdx.x < 64) sS[threadIdx.x] = S[threadIdx.x];
    __syncthreads();

    float l2[NB];
#pragma unroll
    for (int b = 0; b < NB; b++) l2[b] = 0.0f;

    int j = blockIdx.x * blockDim.x + threadIdx.x;
    if (j < L) {
        float pj[NB], cand[NB];
#pragma unroll
        for (int b = 0; b < NB; b++) pj[b] = P[b * L + j];
        unsigned diag = (g_bits[j * WPR + (j >> 5)] >> (j & 31)) & 1u;
        float extra = 1.0f - (float)diag;
        float inv = 1.0f / (g_cnt[j] + extra);
#pragma unroll
        for (int b = 0; b < NB; b++)
            cand[b] = (g_accJ[j * NB + b] + extra * pj[b]) * inv;
#pragma unroll
        for (int b = 0; b < NB; b++) {
            float d = pj[b];
#pragma unroll
            for (int b2 = 0; b2 < NB; b2++) d -= sS[b * NB + b2] * cand[b2];
            l2[b] = d * d;
        }
    }
    // warp reduce, then lane0 atomics
#pragma unroll
    for (int b = 0; b < NB; b++) {
#pragma unroll
        for (int off = 16; off > 0; off >>= 1)
            l2[b] += __shfl_down_sync(0xFFFFFFFFu, l2[b], off);
    }
    if ((threadIdx.x & 31) == 0) {
#pragma unroll
        for (int b = 0; b < NB; b++) atomicAdd(&g_norm2[b], l2[b]);
    }
}

__global__ void k_final(const float* __restrict__ S, float* __restrict__ out) {
    if (threadIdx.x == 0) {
        float total = 0.0f, cnt = 0.0f;
#pragma unroll
        for (int b = 0; b < NB; b++) {
            float rs = 0.0f;
#pragma unroll
            for (int j = 0; j < NB; j++) rs += S[b * NB + j];
            if (rs != 0.0f) { cnt += 1.0f; total += sqrtf(g_norm2[b]); }
        }
        out[0] = (cnt == 0.0f) ? 0.0f : total / fmaxf(cnt, 1.0f);
    }
}

// ---------------------------------------------------------------------
extern "C" void kernel_launch(void* const* d_in, const int* in_sizes, int n_in,
                              void* d_out, int out_size) {
    const float* predicts = (const float*)d_in[0];          // [8, 12288]
    const float* sims     = (const float*)d_in[1];          // [8, 8]
    const float* adj      = (const float*)d_in[2];          // [L, L]
    const void*  mask     = d_in[3];                        // [L, L] bool-ish
    float* out = (float*)d_out;
    (void)in_sizes; (void)n_in; (void)out_size;

    k_zero<<<128, 256>>>();
    k_detect<<<64, 256>>>((const unsigned int*)mask);
    k_convert<<<2048, 256>>>((const unsigned char*)mask);
    k_transpose<<<(L + 255) / 256, 256>>>(predicts);
    k_scan<<<dim3(L / JT, IBS), 256>>>(adj);
    k_finish<<<(L + 255) / 256, 256>>>(predicts, sims);
    k_final<<<1, 32>>>(sims, out);
}

// round 11
// speedup vs baseline: 1.2902x; 1.2902x over previous
#include <cuda_runtime.h>
#include <stdint.h>

#define L 12288
#define NB 8                  // batch
#define WPR (L / 32)          // 384 bit-words per column (rows/32)
#define NWORDS (L * WPR)      // 4,718,592 words = 18.9 MB bit matrix

// -------- static device scratch (no runtime allocation allowed) --------
// Transposed bit matrix: g_bitsT[wi * L + j] bit b  ==  mask[wi*32 + b][j]
__device__ unsigned int g_bitsT[NWORDS];
__device__ __align__(16) float g_accJ[L * NB];   // [j][b] masked-adj-weighted sums
__device__ float g_cnt[L];                       // column counts
__device__ __align__(16) float g_pt[L * NB];     // predicts transposed [i][b]
__device__ float g_norm2[NB];                    // per-batch sum of diff^2
__device__ int g_ff;                             // saw float-1.0 word
__device__ int g_fm;                             // saw multi/odd word (byte layout)

// ---------------------------------------------------------------------
// prep: zero accumulators AND transpose predicts [B][L] -> g_pt [L][B]
__global__ void k_prep(const float* __restrict__ P) {
    const int n = L * NB + L + NB;
    int t0 = blockIdx.x * blockDim.x + threadIdx.x;
    for (int i = t0; i < n; i += gridDim.x * blockDim.x) {
        if (i < L * NB)             g_accJ[i] = 0.0f;
        else if (i < L * NB + L)    g_cnt[i - L * NB] = 0.0f;
        else                        g_norm2[i - L * NB - L] = 0.0f;
    }
    if (t0 < L) {
        int i = t0;
        float4 a, b;
        a.x = P[0 * L + i]; a.y = P[1 * L + i]; a.z = P[2 * L + i]; a.w = P[3 * L + i];
        b.x = P[4 * L + i]; b.y = P[5 * L + i]; b.z = P[6 * L + i]; b.w = P[7 * L + i];
        reinterpret_cast<float4*>(g_pt)[i * 2 + 0] = a;
        reinterpret_cast<float4*>(g_pt)[i * 2 + 1] = b;
    }
    if (blockIdx.x == 0 && threadIdx.x == 0) { g_ff = 0; g_fm = 0; }
}

// Sniff the mask dtype from the first 4 MB viewed as 32-bit words.
// float32 mask: words are 0x00000000 / 0x3F800000.
// int32  mask: words are 0 / 1 only.
// byte   mask: words combine four 0/1 bytes -> values like 0x00010000 appear w.h.p.
__global__ void k_detect(const unsigned int* __restrict__ mw) {
    int ff = 0, fm = 0;
    const int N = 1 << 20;  // 1M words = 4MB, within every candidate layout
    for (int i = blockIdx.x * blockDim.x + threadIdx.x; i < N;
         i += gridDim.x * blockDim.x) {
        unsigned v = mw[i];
        if (v == 0x3F800000u) ff = 1;
        else if (v > 1u) fm = 1;
    }
    if (ff) g_ff = 1;   // racy idempotent stores are fine
    if (fm) g_fm = 1;
}

// pack the nonzero-ness of 4 bytes into a nibble (byte k -> bit k)
__device__ __forceinline__ unsigned nib4(unsigned v) {
    unsigned t = (v & 0x7F7F7F7Fu) + 0x7F7F7F7Fu;
    t = (t | v) & 0x80808080u;   // high bit per byte iff byte nonzero
    t >>= 7;                     // -> 0/1 bytes
    return (t * 0x01020408u) >> 24;  // pack to 4 LSBs
}

// Compress mask -> TRANSPOSED bit matrix via warp ballot bit-transpose.
// Warp handles 32x32-element tiles: lane l owns mask row ti*32+l, builds its
// 32-bit row word for columns [tj*32, tj*32+32), then 32 ballots transpose the
// tile; lane p writes the column word for column tj*32+p (coalesced store).
__global__ __launch_bounds__(256) void k_convert(const unsigned char* __restrict__ maskb) {
    const bool bytemode = (g_fm && !g_ff);
    const int lane = threadIdx.x & 31;
    const int ti = blockIdx.x * 8 + (threadIdx.x >> 5);   // row tile 0..383
    const int r = ti * 32 + lane;                         // this lane's mask row
    const int tj0 = blockIdx.y * 24;                      // column-tile chunk

    for (int tj = tj0; tj < tj0 + 24; tj++) {
        unsigned w;
        if (bytemode) {
            const uint4* p = reinterpret_cast<const uint4*>(maskb + (size_t)r * L + tj * 32);
            uint4 x0 = p[0], x1 = p[1];
            w = nib4(x0.x) | (nib4(x0.y) << 4) | (nib4(x0.z) << 8) |
                (nib4(x0.w) << 12) | (nib4(x1.x) << 16) |
                (nib4(x1.y) << 20) | (nib4(x1.z) << 24) | (nib4(x1.w) << 28);
        } else {
            const uint4* p = reinterpret_cast<const uint4*>(maskb) +
                             ((size_t)r * L + tj * 32) / 4;
            w = 0;
#pragma unroll
            for (int q = 0; q < 8; q++) {
                uint4 x = p[q];
                w |= (x.x ? 1u : 0u) << (4 * q);
                w |= (x.y ? 1u : 0u) << (4 * q + 1);
                w |= (x.z ? 1u : 0u) << (4 * q + 2);
                w |= (x.w ? 1u : 0u) << (4 * q + 3);
            }
        }
        // 32-ballot bit transpose: lane p collects bit p of all lanes' words
        unsigned cw = 0;
#pragma unroll
        for (int p = 0; p < 32; p++) {
            unsigned b = __ballot_sync(0xFFFFFFFFu, (w >> p) & 1u);
            if (lane == p) cw = b;
        }
        // column word for column j = tj*32 + lane, word-row index ti
        g_bitsT[(size_t)ti * L + tj * 32 + lane] = cw;
    }
}

// Column-owned sparse scan: thread owns column j (register accumulators,
// ZERO atomics in the hot loop). grid (48, 16): 16 row-splits for latency hiding.
#define NSPLIT 16
#define WPS (WPR / NSPLIT)   // 24 words per split

__global__ __launch_bounds__(256) void k_scan(const float* __restrict__ adj) {
    const int j = blockIdx.x * blockDim.x + threadIdx.x;   // column 0..L-1
    const int w0 = blockIdx.y * WPS;

    float acc0 = 0.f, acc1 = 0.f, acc2 = 0.f, acc3 = 0.f;
    float acc4 = 0.f, acc5 = 0.f, acc6 = 0.f, acc7 = 0.f;
    float cnt = 0.f;

    for (int wi = w0; wi < w0 + WPS; wi++) {
        unsigned word = g_bitsT[(size_t)wi * L + j];   // coalesced across j
        while (word) {
            int p = __ffs(word) - 1;
            word &= word - 1;
            int i = (wi << 5) + p;
            float a = __ldg(adj + (size_t)i * L + j);
            float4 pA = reinterpret_cast<const float4*>(g_pt)[i * 2 + 0];
            float4 pB = reinterpret_cast<const float4*>(g_pt)[i * 2 + 1];
            acc0 = fmaf(a, pA.x, acc0); acc1 = fmaf(a, pA.y, acc1);
            acc2 = fmaf(a, pA.z, acc2); acc3 = fmaf(a, pA.w, acc3);
            acc4 = fmaf(a, pB.x, acc4); acc5 = fmaf(a, pB.y, acc5);
            acc6 = fmaf(a, pB.z, acc6); acc7 = fmaf(a, pB.w, acc7);
            cnt += 1.0f;
        }
    }
    if (cnt != 0.0f) {
        atomicAdd(&g_cnt[j], cnt);
        float* acc = &g_accJ[j * NB];
        atomicAdd(acc + 0, acc0); atomicAdd(acc + 1, acc1);
        atomicAdd(acc + 2, acc2); atomicAdd(acc + 3, acc3);
        atomicAdd(acc + 4, acc4); atomicAdd(acc + 5, acc5);
        atomicAdd(acc + 6, acc6); atomicAdd(acc + 7, acc7);
    }
}

// candidates -> diff -> per-batch sum of squares
__global__ __launch_bounds__(256) void k_finish(const float* __restrict__ P,
                                                const float* __restrict__ S) {
    __shared__ float sS[64];
    if (threadIdx.x < 64) sS[threadIdx.x] = S[threadIdx.x];
    __syncthreads();

    float l2[NB];
#pragma unroll
    for (int b = 0; b < NB; b++) l2[b] = 0.0f;

    int j = blockIdx.x * blockDim.x + threadIdx.x;
    if (j < L) {
        float pj[NB], cand[NB];
#pragma unroll
        for (int b = 0; b < NB; b++) pj[b] = P[b * L + j];
        // diagonal of the mask: g_bitsT[(j>>5)*L + j] bit (j&31) == mask[j][j]
        unsigned diag = (g_bitsT[(size_t)(j >> 5) * L + j] >> (j & 31)) & 1u;
        float extra = 1.0f - (float)diag;
        float inv = 1.0f / (g_cnt[j] + extra);
#pragma unroll
        for (int b = 0; b < NB; b++)
            cand[b] = (g_accJ[j * NB + b] + extra * pj[b]) * inv;
#pragma unroll
        for (int b = 0; b < NB; b++) {
            float d = pj[b];
#pragma unroll
            for (int b2 = 0; b2 < NB; b2++) d -= sS[b * NB + b2] * cand[b2];
            l2[b] = d * d;
        }
    }
    // warp reduce, then lane0 atomics
#pragma unroll
    for (int b = 0; b < NB; b++) {
#pragma unroll
        for (int off = 16; off > 0; off >>= 1)
            l2[b] += __shfl_down_sync(0xFFFFFFFFu, l2[b], off);
    }
    if ((threadIdx.x & 31) == 0) {
#pragma unroll
        for (int b = 0; b < NB; b++) atomicAdd(&g_norm2[b], l2[b]);
    }
}

__global__ void k_final(const float* __restrict__ S, float* __restrict__ out) {
    if (threadIdx.x == 0) {
        float total = 0.0f, cnt = 0.0f;
#pragma unroll
        for (int b = 0; b < NB; b++) {
            float rs = 0.0f;
#pragma unroll
            for (int j = 0; j < NB; j++) rs += S[b * NB + j];
            if (rs != 0.0f) { cnt += 1.0f; total += sqrtf(g_norm2[b]); }
        }
        out[0] = (cnt == 0.0f) ? 0.0f : total / fmaxf(cnt, 1.0f);
    }
}

// ---------------------------------------------------------------------
extern "C" void kernel_launch(void* const* d_in, const int* in_sizes, int n_in,
                              void* d_out, int out_size) {
    const float* predicts = (const float*)d_in[0];          // [8, 12288]
    const float* sims     = (const float*)d_in[1];          // [8, 8]
    const float* adj      = (const float*)d_in[2];          // [L, L]
    const void*  mask     = d_in[3];                        // [L, L] bool-ish
    float* out = (float*)d_out;
    (void)in_sizes; (void)n_in; (void)out_size;

    k_prep<<<128, 256>>>(predicts);
    k_detect<<<64, 256>>>((const unsigned int*)mask);
    k_convert<<<dim3(48, 16), 256>>>((const unsigned char*)mask);
    k_scan<<<dim3(L / 256, NSPLIT), 256>>>(adj);
    k_finish<<<(L + 255) / 256, 256>>>(predicts, sims);
    k_final<<<1, 32>>>(sims, out);
}

// round 15
// speedup vs baseline: 1.5883x; 1.2310x over previous
#include <cuda_runtime.h>
#include <stdint.h>

#define L 12288
#define NB 8                  // batch
#define WPR (L / 32)          // 384 bit-words per row/column
#define NWORDS (L * WPR)      // 4,718,592 words = 18.9 MB per bit matrix

// -------- static device scratch (no runtime allocation allowed) --------
__device__ unsigned int g_bitsR[NWORDS];  // row-major: [r*WPR + w] bit p == mask[r][w*32+p]
__device__ unsigned int g_bitsT[NWORDS];  // transposed: [wi*L + j] bit b == mask[wi*32+b][j]
__device__ __align__(16) float g_accJ[L * NB];   // [j][b] masked-adj-weighted sums
__device__ float g_cnt[L];                       // column counts
__device__ __align__(16) float g_pt[L * NB];     // predicts transposed [i][b]
__device__ float g_norm2[NB];                    // per-batch sum of diff^2
__device__ int g_ff;                             // saw float-1.0 word
__device__ int g_fm;                             // saw multi/odd word (byte layout)

// ---------------------------------------------------------------------
// prep (blocks 0..127): zero accumulators + transpose predicts [B][L] -> g_pt [L][B]
// detect (blocks 128..191): sniff mask dtype from first 4 MB viewed as words.
//   float32 mask: words are 0x00000000 / 0x3F800000
//   int32  mask: words are 0 / 1 only
//   byte   mask: words combine four 0/1 bytes -> values >1 appear w.h.p.
__global__ void k_prep(const float* __restrict__ P, const unsigned int* __restrict__ mw) {
    if (blockIdx.x < 128) {
        const int n = L * NB + L + NB;
        int t0 = blockIdx.x * blockDim.x + threadIdx.x;
        for (int i = t0; i < n; i += 128 * blockDim.x) {
            if (i < L * NB)             g_accJ[i] = 0.0f;
            else if (i < L * NB + L)    g_cnt[i - L * NB] = 0.0f;
            else                        g_norm2[i - L * NB - L] = 0.0f;
        }
        if (t0 < L) {
            int i = t0;
            float4 a, b;
            a.x = P[0 * L + i]; a.y = P[1 * L + i]; a.z = P[2 * L + i]; a.w = P[3 * L + i];
            b.x = P[4 * L + i]; b.y = P[5 * L + i]; b.z = P[6 * L + i]; b.w = P[7 * L + i];
            reinterpret_cast<float4*>(g_pt)[i * 2 + 0] = a;
            reinterpret_cast<float4*>(g_pt)[i * 2 + 1] = b;
        }
        if (blockIdx.x == 0 && threadIdx.x == 0) { g_ff = 0; g_fm = 0; }
    } else {
        int ff = 0, fm = 0;
        const int N = 1 << 20;  // 1M words = 4MB, within every candidate layout
        int t = (blockIdx.x - 128) * blockDim.x + threadIdx.x;
        for (int i = t; i < N; i += 64 * blockDim.x) {
            unsigned v = mw[i];
            if (v == 0x3F800000u) ff = 1;
            else if (v > 1u) fm = 1;
        }
        if (ff) g_ff = 1;   // racy idempotent stores are fine
        if (fm) g_fm = 1;
    }
}

// pack the nonzero-ness of 4 bytes into a nibble (byte k -> bit k)
__device__ __forceinline__ unsigned nib4(unsigned v) {
    unsigned t = (v & 0x7F7F7F7Fu) + 0x7F7F7F7Fu;
    t = (t | v) & 0x80808080u;   // high bit per byte iff byte nonzero
    t >>= 7;                     // -> 0/1 bytes
    return (t * 0x01020408u) >> 24;  // pack to 4 LSBs
}

// Pass A: mask -> ROW-major bit matrix.
// Word-mode: warp-cooperative ballot pack. 32 lanes load 32 consecutive 4-byte
// elements (one coalesced 128B line); one ballot(v!=0) = one 32-bit word.
// Byte-mode: lane packs its own 32 consecutive bytes (2x uint4, coalesced).
// grid (WPR/32=12, L/8=1536), 256 threads; warp handles (row, 32-word chunk).
__global__ __launch_bounds__(256) void k_pack(const void* __restrict__ mask) {
    const bool bytemode = (g_fm && !g_ff);
    const int lane = threadIdx.x & 31;
    const int r = blockIdx.y * 8 + (threadIdx.x >> 5);   // row 0..L-1
    const int chunk = blockIdx.x;                        // 0..11

    if (bytemode) {
        const unsigned char* mb = (const unsigned char*)mask;
        int w = chunk * 32 + lane;
        const uint4* p = reinterpret_cast<const uint4*>(mb + (size_t)r * L + (size_t)w * 32);
        uint4 x0 = p[0], x1 = p[1];
        unsigned bits = nib4(x0.x) | (nib4(x0.y) << 4) | (nib4(x0.z) << 8) |
                        (nib4(x0.w) << 12) | (nib4(x1.x) << 16) |
                        (nib4(x1.y) << 20) | (nib4(x1.z) << 24) | (nib4(x1.w) << 28);
        g_bitsR[(size_t)r * WPR + w] = bits;
    } else {
        const unsigned* base = (const unsigned*)mask + (size_t)r * L + chunk * 1024 + lane;
        unsigned cw = 0;
#pragma unroll
        for (int k = 0; k < 32; k++) {
            unsigned v = __ldg(base + k * 32);
            unsigned b = __ballot_sync(0xFFFFFFFFu, v != 0u);
            if (lane == k) cw = b;
        }
        g_bitsR[(size_t)r * WPR + chunk * 32 + lane] = cw;   // coalesced
    }
}

// Pass B: bit transpose g_bitsR -> g_bitsT via 32x32 ballot tiles.
// Warp: lane l covers row ti*32+l, loads 8 consecutive words (2x uint4 = full
// 32B sector), transposes 8 tiles, coalesced column-word stores.
// grid (WPR/8=48, 384/8=48), 256 threads.
__global__ __launch_bounds__(256) void k_bitT() {
    const int lane = threadIdx.x & 31;
    const int ti = blockIdx.y * 8 + (threadIdx.x >> 5);   // row tile 0..383
    const int tw0 = blockIdx.x * 8;                       // word-col base
    const int r = ti * 32 + lane;

    uint4 a = *reinterpret_cast<const uint4*>(&g_bitsR[(size_t)r * WPR + tw0]);
    uint4 b = *reinterpret_cast<const uint4*>(&g_bitsR[(size_t)r * WPR + tw0 + 4]);
    unsigned ws[8] = {a.x, a.y, a.z, a.w, b.x, b.y, b.z, b.w};

#pragma unroll
    for (int t = 0; t < 8; t++) {
        unsigned w = ws[t];
        unsigned cw = 0;
#pragma unroll
        for (int p = 0; p < 32; p++) {
            unsigned bb = __ballot_sync(0xFFFFFFFFu, (w >> p) & 1u);
            if (lane == p) cw = bb;
        }
        // column word for column j = (tw0+t)*32 + lane, word-row ti
        g_bitsT[(size_t)ti * L + (tw0 + t) * 32 + lane] = cw;   // coalesced
    }
}

// Column-owned sparse scan: thread owns column j (register accumulators,
// ZERO atomics in the hot loop). 32 row-splits -> ~8 blocks/SM, full occupancy.
#define NSPLIT 32
#define WPS (WPR / NSPLIT)   // 12 words per split

__global__ __launch_bounds__(256) void k_scan(const float* __restrict__ adj) {
    const int j = blockIdx.x * blockDim.x + threadIdx.x;   // column 0..L-1
    const int w0 = blockIdx.y * WPS;

    float acc0 = 0.f, acc1 = 0.f, acc2 = 0.f, acc3 = 0.f;
    float acc4 = 0.f, acc5 = 0.f, acc6 = 0.f, acc7 = 0.f;
    float cnt = 0.f;

    for (int wi = w0; wi < w0 + WPS; wi++) {
        unsigned word = g_bitsT[(size_t)wi * L + j];   // coalesced across j
        while (word) {
            int p = __ffs(word) - 1;
            word &= word - 1;
            int i = (wi << 5) + p;
            float a = __ldg(adj + (size_t)i * L + j);
            float4 pA = reinterpret_cast<const float4*>(g_pt)[i * 2 + 0];
            float4 pB = reinterpret_cast<const float4*>(g_pt)[i * 2 + 1];
            acc0 = fmaf(a, pA.x, acc0); acc1 = fmaf(a, pA.y, acc1);
            acc2 = fmaf(a, pA.z, acc2); acc3 = fmaf(a, pA.w, acc3);
            acc4 = fmaf(a, pB.x, acc4); acc5 = fmaf(a, pB.y, acc5);
            acc6 = fmaf(a, pB.z, acc6); acc7 = fmaf(a, pB.w, acc7);
            cnt += 1.0f;
        }
    }
    if (cnt != 0.0f) {
        atomicAdd(&g_cnt[j], cnt);
        float* acc = &g_accJ[j * NB];
        atomicAdd(acc + 0, acc0); atomicAdd(acc + 1, acc1);
        atomicAdd(acc + 2, acc2); atomicAdd(acc + 3, acc3);
        atomicAdd(acc + 4, acc4); atomicAdd(acc + 5, acc5);
        atomicAdd(acc + 6, acc6); atomicAdd(acc + 7, acc7);
    }
}

// candidates -> diff -> per-batch sum of squares
__global__ __launch_bounds__(256) void k_finish(const float* __restrict__ P,
                                                const float* __restrict__ S) {
    __shared__ float sS[64];
    if (threadIdx.x < 64) sS[threadIdx.x] = S[threadIdx.x];
    __syncthreads();

    float l2[NB];
#pragma unroll
    for (int b = 0; b < NB; b++) l2[b] = 0.0f;

    int j = blockIdx.x * blockDim.x + threadIdx.x;
    if (j < L) {
        float pj[NB], cand[NB];
#pragma unroll
        for (int b = 0; b < NB; b++) pj[b] = P[b * L + j];
        // diagonal of the mask: g_bitsT[(j>>5)*L + j] bit (j&31) == mask[j][j]
        unsigned diag = (g_bitsT[(size_t)(j >> 5) * L + j] >> (j & 31)) & 1u;
        float extra = 1.0f - (float)diag;
        float inv = 1.0f / (g_cnt[j] + extra);
#pragma unroll
        for (int b = 0; b < NB; b++)
            cand[b] = (g_accJ[j * NB + b] + extra * pj[b]) * inv;
#pragma unroll
        for (int b = 0; b < NB; b++) {
            float d = pj[b];
#pragma unroll
            for (int b2 = 0; b2 < NB; b2++) d -= sS[b * NB + b2] * cand[b2];
            l2[b] = d * d;
        }
    }
    // warp reduce, then lane0 atomics
#pragma unroll
    for (int b = 0; b < NB; b++) {
#pragma unroll
        for (int off = 16; off > 0; off >>= 1)
            l2[b] += __shfl_down_sync(0xFFFFFFFFu, l2[b], off);
    }
    if ((threadIdx.x & 31) == 0) {
#pragma unroll
        for (int b = 0; b < NB; b++) atomicAdd(&g_norm2[b], l2[b]);
    }
}

__global__ void k_final(const float* __restrict__ S, float* __restrict__ out) {
    if (threadIdx.x == 0) {
        float total = 0.0f, cnt = 0.0f;
#pragma unroll
        for (int b = 0; b < NB; b++) {
            float rs = 0.0f;
#pragma unroll
            for (int j = 0; j < NB; j++) rs += S[b * NB + j];
            if (rs != 0.0f) { cnt += 1.0f; total += sqrtf(g_norm2[b]); }
        }
        out[0] = (cnt == 0.0f) ? 0.0f : total / fmaxf(cnt, 1.0f);
    }
}

// ---------------------------------------------------------------------
extern "C" void kernel_launch(void* const* d_in, const int* in_sizes, int n_in,
                              void* d_out, int out_size) {
    const float* predicts = (const float*)d_in[0];          // [8, 12288]
    const float* sims     = (const float*)d_in[1];          // [8, 8]
    const float* adj      = (const float*)d_in[2];          // [L, L]
    const void*  mask     = d_in[3];                        // [L, L] bool-ish
    float* out = (float*)d_out;
    (void)in_sizes; (void)n_in; (void)out_size;

    k_prep<<<192, 256>>>(predicts, (const unsigned int*)mask);
    k_pack<<<dim3(WPR / 32, L / 8), 256>>>(mask);
    k_bitT<<<dim3(WPR / 8, 48), 256>>>();
    k_scan<<<dim3(L / 256, NSPLIT), 256>>>(adj);
    k_finish<<<(L + 255) / 256, 256>>>(predicts, sims);
    k_final<<<1, 32>>>(sims, out);
}